// round 13
// baseline (speedup 1.0000x reference)
#include <cuda_runtime.h>

// B=2, N=64, H=512, W=512, complex pixels.
// f_ipt  [2, 512, 512, 2]      f32
// f_y    [2, 64, 512, 512, 2]  f32   (268 MB - pure stream, evict_first)
// Hreal  [64, 512, 512, 2]     f32   (134 MB; partially pinned in L2)
// NBFkeep: int scalar in d_in[3]
// out    [2, 512, 512, 2]      f32
//
// g_b = (1/N) * sum_n conj(H_n) * (H_n * x_b - y_{b,n})
//
// Two-pool L2 pinning across CUDA-graph replays:
//  - frames 0..23  (50 MB): evict_last policy  -> protected pool (~63 MB cap,
//    R12 showed 84 MB cyclic thrashes it to ~0%)
//  - frames 24..47 (50 MB): __ldcg normal      -> ~58% survives (R9-measured)
//  - frames 48..63 + f_y + stores: evict-first streaming
// Expected steady-state DRAM traffic ~419 -> ~340 MB per replay.
// Kernel body: proven R3 shape (1 float4/thread, both batches fused,
// 3x LDG.128 per iter, unroll 4, 128-thread blocks).

typedef unsigned long long u64;

#define HW      (512 * 512)      // complex pixels per image
#define HW4     (HW / 2)         // float4 units per image
#define NFRAMES 64
#define N_EL    24               // frames pinned evict_last (50 MB)
#define N_CG    48               // frames [N_EL, N_CG) use __ldcg (50 MB)

// evict_last policy-hinted 128-bit non-coherent load
__device__ __forceinline__ float4 ldg_evict_last(const float4* p, u64 pol) {
    float4 v;
    asm volatile("ld.global.nc.L2::cache_hint.v4.f32 {%0,%1,%2,%3}, [%4], %5;"
                 : "=f"(v.x), "=f"(v.y), "=f"(v.z), "=f"(v.w)
                 : "l"(p), "l"(pol));
    return v;
}

__device__ __forceinline__ void cstep4(const float4 Hv, const float4 x0, const float4 x1,
                                       const float4 y0, const float4 y1,
                                       float4& acc0, float4& acc1) {
    // pixel A = (.x,.y), pixel B = (.z,.w)
    {   // batch 0, pixel A
        float zr = Hv.x * x0.x - Hv.y * x0.y;
        float zi = Hv.x * x0.y + Hv.y * x0.x;
        float dr = zr - y0.x;
        float di = zi - y0.y;
        acc0.x += Hv.x * dr + Hv.y * di;
        acc0.y += Hv.x * di - Hv.y * dr;
    }
    {   // batch 0, pixel B
        float zr = Hv.z * x0.z - Hv.w * x0.w;
        float zi = Hv.z * x0.w + Hv.w * x0.z;
        float dr = zr - y0.z;
        float di = zi - y0.w;
        acc0.z += Hv.z * dr + Hv.w * di;
        acc0.w += Hv.z * di - Hv.w * dr;
    }
    {   // batch 1, pixel A
        float zr = Hv.x * x1.x - Hv.y * x1.y;
        float zi = Hv.x * x1.y + Hv.y * x1.x;
        float dr = zr - y1.x;
        float di = zi - y1.y;
        acc1.x += Hv.x * dr + Hv.y * di;
        acc1.y += Hv.x * di - Hv.y * dr;
    }
    {   // batch 1, pixel B
        float zr = Hv.z * x1.z - Hv.w * x1.w;
        float zi = Hv.z * x1.w + Hv.w * x1.z;
        float dr = zr - y1.z;
        float di = zi - y1.w;
        acc1.z += Hv.z * dr + Hv.w * di;
        acc1.w += Hv.z * di - Hv.w * dr;
    }
}

__global__ __launch_bounds__(128) void idt_backproj_kernel(
    const float4* __restrict__ x,   // f_ipt  [2][HW4]
    const float4* __restrict__ y,   // f_y    [2][NFRAMES][HW4]
    const float4* __restrict__ Hm,  // Hreal  [NFRAMES][HW4]
    const int*    __restrict__ nbf, // scalar
    float4*       __restrict__ out) // [2][HW4]
{
    const int p = blockIdx.x * blockDim.x + threadIdx.x;

    // evict_last allocation policy for the protected H frames
    u64 pol;
    asm volatile("createpolicy.fractional.L2::evict_last.b64 %0, 1.0;" : "=l"(pol));

    const float4 x0 = x[p];
    const float4 x1 = x[HW4 + p];

    float4 acc0 = make_float4(0.f, 0.f, 0.f, 0.f);
    float4 acc1 = make_float4(0.f, 0.f, 0.f, 0.f);

    const float4* Hp  = Hm + p;
    const float4* y0p = y + p;                              // batch 0
    const float4* y1p = y + (size_t)NFRAMES * HW4 + p;      // batch 1

    // Frames 0..N_EL-1: evict_last protected pool
#pragma unroll 4
    for (int n = 0; n < N_EL; n++) {
        const size_t off = (size_t)n * HW4;
        const float4 Hv = ldg_evict_last(Hp + off, pol);
        const float4 y0 = __ldcs(y0p + off);
        const float4 y1 = __ldcs(y1p + off);
        cstep4(Hv, x0, x1, y0, y1, acc0, acc1);
    }

    // Frames N_EL..N_CG-1: normal-priority (partial L2 survival)
#pragma unroll 4
    for (int n = N_EL; n < N_CG; n++) {
        const size_t off = (size_t)n * HW4;
        const float4 Hv = __ldcg(Hp + off);
        const float4 y0 = __ldcs(y0p + off);
        const float4 y1 = __ldcs(y1p + off);
        cstep4(Hv, x0, x1, y0, y1, acc0, acc1);
    }

    // Frames N_CG..63: everything streams evict-first
#pragma unroll 4
    for (int n = N_CG; n < NFRAMES; n++) {
        const size_t off = (size_t)n * HW4;
        const float4 Hv = __ldcs(Hp  + off);
        const float4 y0 = __ldcs(y0p + off);
        const float4 y1 = __ldcs(y1p + off);
        cstep4(Hv, x0, x1, y0, y1, acc0, acc1);
    }

    const float scale = 1.0f / (float)(*nbf);
    acc0.x *= scale; acc0.y *= scale; acc0.z *= scale; acc0.w *= scale;
    acc1.x *= scale; acc1.y *= scale; acc1.z *= scale; acc1.w *= scale;

    __stcs(out + p,       acc0);
    __stcs(out + HW4 + p, acc1);
}

extern "C" void kernel_launch(void* const* d_in, const int* in_sizes, int n_in,
                              void* d_out, int out_size) {
    const float4* x   = (const float4*)d_in[0];
    const float4* y   = (const float4*)d_in[1];
    const float4* Hm  = (const float4*)d_in[2];
    const int*    nbf = (const int*)d_in[3];
    float4*       out = (float4*)d_out;

    const int threads = 128;
    const int blocks  = HW4 / threads;  // 1024
    idt_backproj_kernel<<<blocks, threads>>>(x, y, Hm, nbf, out);
}

// round 14
// speedup vs baseline: 1.0664x; 1.0664x over previous
#include <cuda_runtime.h>

// B=2, N=64, H=512, W=512, complex pixels.
// f_ipt  [2, 512, 512, 2]      f32
// f_y    [2, 64, 512, 512, 2]  f32   (268 MB - pure stream, evict_first)
// Hreal  [64, 512, 512, 2]     f32   (134 MB; frames 0..NPIN-1 L2-retained)
// NBFkeep: int scalar in d_in[3]
// out    [2, 512, 512, 2]      f32
//
// g_b = (1/N) * sum_n conj(H_n) * (H_n * x_b - y_{b,n})
//
// Cross-replay L2 retention via __ldcg (normal priority) — the only working
// mechanism (evict_last needs a persisting-L2 carveout we cannot set; R12/R13
// proved it regresses without one). Measured curve: 0 frames -> 64.0us,
// 32 frames (67 MB) -> 58.1us, 64 frames (134 MB) -> 66.0us (thrash).
// This round probes NPIN=40 (84 MB) to locate the peak.
// Kernel body: proven R3 shape (1 float4/thread, both batches fused,
// 3x LDG.128 per iter, unroll 4, 128-thread blocks).

#define HW      (512 * 512)      // complex pixels per image
#define HW4     (HW / 2)         // float4 units per image
#define NFRAMES 64
#define NPIN    40               // frames of H kept L2-resident via __ldcg (84 MB)

__device__ __forceinline__ void cstep4(const float4 Hv, const float4 x0, const float4 x1,
                                       const float4 y0, const float4 y1,
                                       float4& acc0, float4& acc1) {
    // pixel A = (.x,.y), pixel B = (.z,.w)
    {   // batch 0, pixel A
        float zr = Hv.x * x0.x - Hv.y * x0.y;
        float zi = Hv.x * x0.y + Hv.y * x0.x;
        float dr = zr - y0.x;
        float di = zi - y0.y;
        acc0.x += Hv.x * dr + Hv.y * di;
        acc0.y += Hv.x * di - Hv.y * dr;
    }
    {   // batch 0, pixel B
        float zr = Hv.z * x0.z - Hv.w * x0.w;
        float zi = Hv.z * x0.w + Hv.w * x0.z;
        float dr = zr - y0.z;
        float di = zi - y0.w;
        acc0.z += Hv.z * dr + Hv.w * di;
        acc0.w += Hv.z * di - Hv.w * dr;
    }
    {   // batch 1, pixel A
        float zr = Hv.x * x1.x - Hv.y * x1.y;
        float zi = Hv.x * x1.y + Hv.y * x1.x;
        float dr = zr - y1.x;
        float di = zi - y1.y;
        acc1.x += Hv.x * dr + Hv.y * di;
        acc1.y += Hv.x * di - Hv.y * dr;
    }
    {   // batch 1, pixel B
        float zr = Hv.z * x1.z - Hv.w * x1.w;
        float zi = Hv.z * x1.w + Hv.w * x1.z;
        float dr = zr - y1.z;
        float di = zi - y1.w;
        acc1.z += Hv.z * dr + Hv.w * di;
        acc1.w += Hv.z * di - Hv.w * dr;
    }
}

__global__ __launch_bounds__(128) void idt_backproj_kernel(
    const float4* __restrict__ x,   // f_ipt  [2][HW4]
    const float4* __restrict__ y,   // f_y    [2][NFRAMES][HW4]
    const float4* __restrict__ Hm,  // Hreal  [NFRAMES][HW4]
    const int*    __restrict__ nbf, // scalar
    float4*       __restrict__ out) // [2][HW4]
{
    const int p = blockIdx.x * blockDim.x + threadIdx.x;

    const float4 x0 = x[p];
    const float4 x1 = x[HW4 + p];

    float4 acc0 = make_float4(0.f, 0.f, 0.f, 0.f);
    float4 acc1 = make_float4(0.f, 0.f, 0.f, 0.f);

    const float4* Hp  = Hm + p;
    const float4* y0p = y + p;                              // batch 0
    const float4* y1p = y + (size_t)NFRAMES * HW4 + p;      // batch 1

    // Frames 0..NPIN-1: H via normal-policy load -> L2-retained across replays
#pragma unroll 4
    for (int n = 0; n < NPIN; n++) {
        const size_t off = (size_t)n * HW4;
        const float4 Hv = __ldcg(Hp  + off);
        const float4 y0 = __ldcs(y0p + off);
        const float4 y1 = __ldcs(y1p + off);
        cstep4(Hv, x0, x1, y0, y1, acc0, acc1);
    }

    // Frames NPIN..63: everything streams evict-first
#pragma unroll 4
    for (int n = NPIN; n < NFRAMES; n++) {
        const size_t off = (size_t)n * HW4;
        const float4 Hv = __ldcs(Hp  + off);
        const float4 y0 = __ldcs(y0p + off);
        const float4 y1 = __ldcs(y1p + off);
        cstep4(Hv, x0, x1, y0, y1, acc0, acc1);
    }

    const float scale = 1.0f / (float)(*nbf);
    acc0.x *= scale; acc0.y *= scale; acc0.z *= scale; acc0.w *= scale;
    acc1.x *= scale; acc1.y *= scale; acc1.z *= scale; acc1.w *= scale;

    __stcs(out + p,       acc0);
    __stcs(out + HW4 + p, acc1);
}

extern "C" void kernel_launch(void* const* d_in, const int* in_sizes, int n_in,
                              void* d_out, int out_size) {
    const float4* x   = (const float4*)d_in[0];
    const float4* y   = (const float4*)d_in[1];
    const float4* Hm  = (const float4*)d_in[2];
    const int*    nbf = (const int*)d_in[3];
    float4*       out = (float4*)d_out;

    const int threads = 128;
    const int blocks  = HW4 / threads;  // 1024
    idt_backproj_kernel<<<blocks, threads>>>(x, y, Hm, nbf, out);
}

// round 15
// speedup vs baseline: 1.1134x; 1.0441x over previous
#include <cuda_runtime.h>

// B=2, N=64, H=512, W=512, complex pixels.
// f_ipt  [2, 512, 512, 2]      f32
// f_y    [2, 64, 512, 512, 2]  f32   (268 MB - pure stream, evict_first)
// Hreal  [64, 512, 512, 2]     f32   (134 MB; frames 0..NPIN-1 L2-retained)
// NBFkeep: int scalar in d_in[3]
// out    [2, 512, 512, 2]      f32
//
// g_b = (1/N) * sum_n conj(H_n) * (H_n * x_b - y_{b,n})
//
// Cross-replay L2 retention via __ldcg (normal priority) — the only working
// mechanism (evict_last needs a persisting-L2 carveout we cannot set; R12/R13
// proved it regresses without one). Measured curve: 0 frames -> 64.0us,
// 32 frames (67 MB) -> 58.1us, 64 frames (134 MB) -> 66.0us (thrash).
// This round probes NPIN=40 (84 MB) to locate the peak.
// Kernel body: proven R3 shape (1 float4/thread, both batches fused,
// 3x LDG.128 per iter, unroll 4, 128-thread blocks).

#define HW      (512 * 512)      // complex pixels per image
#define HW4     (HW / 2)         // float4 units per image
#define NFRAMES 64
#define NPIN    40               // frames of H kept L2-resident via __ldcg (84 MB)

__device__ __forceinline__ void cstep4(const float4 Hv, const float4 x0, const float4 x1,
                                       const float4 y0, const float4 y1,
                                       float4& acc0, float4& acc1) {
    // pixel A = (.x,.y), pixel B = (.z,.w)
    {   // batch 0, pixel A
        float zr = Hv.x * x0.x - Hv.y * x0.y;
        float zi = Hv.x * x0.y + Hv.y * x0.x;
        float dr = zr - y0.x;
        float di = zi - y0.y;
        acc0.x += Hv.x * dr + Hv.y * di;
        acc0.y += Hv.x * di - Hv.y * dr;
    }
    {   // batch 0, pixel B
        float zr = Hv.z * x0.z - Hv.w * x0.w;
        float zi = Hv.z * x0.w + Hv.w * x0.z;
        float dr = zr - y0.z;
        float di = zi - y0.w;
        acc0.z += Hv.z * dr + Hv.w * di;
        acc0.w += Hv.z * di - Hv.w * dr;
    }
    {   // batch 1, pixel A
        float zr = Hv.x * x1.x - Hv.y * x1.y;
        float zi = Hv.x * x1.y + Hv.y * x1.x;
        float dr = zr - y1.x;
        float di = zi - y1.y;
        acc1.x += Hv.x * dr + Hv.y * di;
        acc1.y += Hv.x * di - Hv.y * dr;
    }
    {   // batch 1, pixel B
        float zr = Hv.z * x1.z - Hv.w * x1.w;
        float zi = Hv.z * x1.w + Hv.w * x1.z;
        float dr = zr - y1.z;
        float di = zi - y1.w;
        acc1.z += Hv.z * dr + Hv.w * di;
        acc1.w += Hv.z * di - Hv.w * dr;
    }
}

__global__ __launch_bounds__(128) void idt_backproj_kernel(
    const float4* __restrict__ x,   // f_ipt  [2][HW4]
    const float4* __restrict__ y,   // f_y    [2][NFRAMES][HW4]
    const float4* __restrict__ Hm,  // Hreal  [NFRAMES][HW4]
    const int*    __restrict__ nbf, // scalar
    float4*       __restrict__ out) // [2][HW4]
{
    const int p = blockIdx.x * blockDim.x + threadIdx.x;

    const float4 x0 = x[p];
    const float4 x1 = x[HW4 + p];

    float4 acc0 = make_float4(0.f, 0.f, 0.f, 0.f);
    float4 acc1 = make_float4(0.f, 0.f, 0.f, 0.f);

    const float4* Hp  = Hm + p;
    const float4* y0p = y + p;                              // batch 0
    const float4* y1p = y + (size_t)NFRAMES * HW4 + p;      // batch 1

    // Frames 0..NPIN-1: H via normal-policy load -> L2-retained across replays
#pragma unroll 4
    for (int n = 0; n < NPIN; n++) {
        const size_t off = (size_t)n * HW4;
        const float4 Hv = __ldcg(Hp  + off);
        const float4 y0 = __ldcs(y0p + off);
        const float4 y1 = __ldcs(y1p + off);
        cstep4(Hv, x0, x1, y0, y1, acc0, acc1);
    }

    // Frames NPIN..63: everything streams evict-first
#pragma unroll 4
    for (int n = NPIN; n < NFRAMES; n++) {
        const size_t off = (size_t)n * HW4;
        const float4 Hv = __ldcs(Hp  + off);
        const float4 y0 = __ldcs(y0p + off);
        const float4 y1 = __ldcs(y1p + off);
        cstep4(Hv, x0, x1, y0, y1, acc0, acc1);
    }

    const float scale = 1.0f / (float)(*nbf);
    acc0.x *= scale; acc0.y *= scale; acc0.z *= scale; acc0.w *= scale;
    acc1.x *= scale; acc1.y *= scale; acc1.z *= scale; acc1.w *= scale;

    __stcs(out + p,       acc0);
    __stcs(out + HW4 + p, acc1);
}

extern "C" void kernel_launch(void* const* d_in, const int* in_sizes, int n_in,
                              void* d_out, int out_size) {
    const float4* x   = (const float4*)d_in[0];
    const float4* y   = (const float4*)d_in[1];
    const float4* Hm  = (const float4*)d_in[2];
    const int*    nbf = (const int*)d_in[3];
    float4*       out = (float4*)d_out;

    const int threads = 128;
    const int blocks  = HW4 / threads;  // 1024
    idt_backproj_kernel<<<blocks, threads>>>(x, y, Hm, nbf, out);
}

// round 16
// speedup vs baseline: 1.1152x; 1.0016x over previous
#include <cuda_runtime.h>

// B=2, N=64, H=512, W=512, complex pixels.
// f_ipt  [2, 512, 512, 2]      f32
// f_y    [2, 64, 512, 512, 2]  f32   (268 MB - pure stream, evict_first)
// Hreal  [64, 512, 512, 2]     f32   (134 MB; frames 0..NPIN-1 L2-retained)
// NBFkeep: int scalar in d_in[3]
// out    [2, 512, 512, 2]      f32
//
// g_b = (1/N) * sum_n conj(H_n) * (H_n * x_b - y_{b,n})
//
// Cross-replay L2 retention via __ldcg (normal priority) — the only working
// mechanism on this part (evict_last needs a persisting-L2 carveout the
// harness forbids setting; it regresses without one, R12/R13).
// Measured NPIN curve: 0 -> 64.0us, 32 -> 57.9-58.1us, 40 -> 59.6us,
// 64 -> 66.0us. This round probes the left side with NPIN=24 (50 MB):
// if per-set overflow limited retention at 67 MB, a cleanly-fitting 50 MB
// set retains ~85%+ and beats the peak.
// Kernel body: proven R3 shape (1 float4/thread, both batches fused,
// 3x LDG.128 per iter, unroll 4, 128-thread blocks).

#define HW      (512 * 512)      // complex pixels per image
#define HW4     (HW / 2)         // float4 units per image
#define NFRAMES 64
#define NPIN    24               // frames of H kept L2-resident via __ldcg (50 MB)

__device__ __forceinline__ void cstep4(const float4 Hv, const float4 x0, const float4 x1,
                                       const float4 y0, const float4 y1,
                                       float4& acc0, float4& acc1) {
    // pixel A = (.x,.y), pixel B = (.z,.w)
    {   // batch 0, pixel A
        float zr = Hv.x * x0.x - Hv.y * x0.y;
        float zi = Hv.x * x0.y + Hv.y * x0.x;
        float dr = zr - y0.x;
        float di = zi - y0.y;
        acc0.x += Hv.x * dr + Hv.y * di;
        acc0.y += Hv.x * di - Hv.y * dr;
    }
    {   // batch 0, pixel B
        float zr = Hv.z * x0.z - Hv.w * x0.w;
        float zi = Hv.z * x0.w + Hv.w * x0.z;
        float dr = zr - y0.z;
        float di = zi - y0.w;
        acc0.z += Hv.z * dr + Hv.w * di;
        acc0.w += Hv.z * di - Hv.w * dr;
    }
    {   // batch 1, pixel A
        float zr = Hv.x * x1.x - Hv.y * x1.y;
        float zi = Hv.x * x1.y + Hv.y * x1.x;
        float dr = zr - y1.x;
        float di = zi - y1.y;
        acc1.x += Hv.x * dr + Hv.y * di;
        acc1.y += Hv.x * di - Hv.y * dr;
    }
    {   // batch 1, pixel B
        float zr = Hv.z * x1.z - Hv.w * x1.w;
        float zi = Hv.z * x1.w + Hv.w * x1.z;
        float dr = zr - y1.z;
        float di = zi - y1.w;
        acc1.z += Hv.z * dr + Hv.w * di;
        acc1.w += Hv.z * di - Hv.w * dr;
    }
}

__global__ __launch_bounds__(128) void idt_backproj_kernel(
    const float4* __restrict__ x,   // f_ipt  [2][HW4]
    const float4* __restrict__ y,   // f_y    [2][NFRAMES][HW4]
    const float4* __restrict__ Hm,  // Hreal  [NFRAMES][HW4]
    const int*    __restrict__ nbf, // scalar
    float4*       __restrict__ out) // [2][HW4]
{
    const int p = blockIdx.x * blockDim.x + threadIdx.x;

    const float4 x0 = x[p];
    const float4 x1 = x[HW4 + p];

    float4 acc0 = make_float4(0.f, 0.f, 0.f, 0.f);
    float4 acc1 = make_float4(0.f, 0.f, 0.f, 0.f);

    const float4* Hp  = Hm + p;
    const float4* y0p = y + p;                              // batch 0
    const float4* y1p = y + (size_t)NFRAMES * HW4 + p;      // batch 1

    // Frames 0..NPIN-1: H via normal-policy load -> L2-retained across replays
#pragma unroll 4
    for (int n = 0; n < NPIN; n++) {
        const size_t off = (size_t)n * HW4;
        const float4 Hv = __ldcg(Hp  + off);
        const float4 y0 = __ldcs(y0p + off);
        const float4 y1 = __ldcs(y1p + off);
        cstep4(Hv, x0, x1, y0, y1, acc0, acc1);
    }

    // Frames NPIN..63: everything streams evict-first
#pragma unroll 4
    for (int n = NPIN; n < NFRAMES; n++) {
        const size_t off = (size_t)n * HW4;
        const float4 Hv = __ldcs(Hp  + off);
        const float4 y0 = __ldcs(y0p + off);
        const float4 y1 = __ldcs(y1p + off);
        cstep4(Hv, x0, x1, y0, y1, acc0, acc1);
    }

    const float scale = 1.0f / (float)(*nbf);
    acc0.x *= scale; acc0.y *= scale; acc0.z *= scale; acc0.w *= scale;
    acc1.x *= scale; acc1.y *= scale; acc1.z *= scale; acc1.w *= scale;

    __stcs(out + p,       acc0);
    __stcs(out + HW4 + p, acc1);
}

extern "C" void kernel_launch(void* const* d_in, const int* in_sizes, int n_in,
                              void* d_out, int out_size) {
    const float4* x   = (const float4*)d_in[0];
    const float4* y   = (const float4*)d_in[1];
    const float4* Hm  = (const float4*)d_in[2];
    const int*    nbf = (const int*)d_in[3];
    float4*       out = (float4*)d_out;

    const int threads = 128;
    const int blocks  = HW4 / threads;  // 1024
    idt_backproj_kernel<<<blocks, threads>>>(x, y, Hm, nbf, out);
}

// round 17
// speedup vs baseline: 1.1460x; 1.0277x over previous
#include <cuda_runtime.h>

// B=2, N=64, H=512, W=512, complex pixels.
// f_ipt  [2, 512, 512, 2]      f32
// f_y    [2, 64, 512, 512, 2]  f32   (268 MB - pure stream, evict_first)
// Hreal  [64, 512, 512, 2]     f32   (134 MB; frames 0..31 L2-retained)
// NBFkeep: int scalar in d_in[3]
// out    [2, 512, 512, 2]      f32   (write-through, no L2 allocation)
//
// g_b = (1/N) * sum_n conj(H_n) * (H_n * x_b - y_{b,n})
//
// Final configuration. Cross-replay L2 retention via __ldcg on 32 H-frames
// (67 MB) — measured optimum of the NPIN curve:
//   0 -> 64.0us, 24 -> 59.5us, 32 -> 57.9us, 40 -> 59.6us, 64 -> 66.0us.
// (evict_last policies regress without a persisting-L2 carveout, which the
// harness forbids setting: R12/R13.) Output stores are write-through (__stwt)
// so the 4 MB result no longer allocates L2 lines against the pinned set.
// Kernel body: proven R3 shape (1 float4/thread = 2 complex pixels, both
// batches fused so H is read once, 3x LDG.128 per iter, unroll 4,
// 128-thread blocks).

#define HW      (512 * 512)      // complex pixels per image
#define HW4     (HW / 2)         // float4 units per image
#define NFRAMES 64
#define NPIN    32               // frames of H kept L2-resident via __ldcg (67 MB)

__device__ __forceinline__ void cstep4(const float4 Hv, const float4 x0, const float4 x1,
                                       const float4 y0, const float4 y1,
                                       float4& acc0, float4& acc1) {
    // pixel A = (.x,.y), pixel B = (.z,.w)
    {   // batch 0, pixel A
        float zr = Hv.x * x0.x - Hv.y * x0.y;
        float zi = Hv.x * x0.y + Hv.y * x0.x;
        float dr = zr - y0.x;
        float di = zi - y0.y;
        acc0.x += Hv.x * dr + Hv.y * di;
        acc0.y += Hv.x * di - Hv.y * dr;
    }
    {   // batch 0, pixel B
        float zr = Hv.z * x0.z - Hv.w * x0.w;
        float zi = Hv.z * x0.w + Hv.w * x0.z;
        float dr = zr - y0.z;
        float di = zi - y0.w;
        acc0.z += Hv.z * dr + Hv.w * di;
        acc0.w += Hv.z * di - Hv.w * dr;
    }
    {   // batch 1, pixel A
        float zr = Hv.x * x1.x - Hv.y * x1.y;
        float zi = Hv.x * x1.y + Hv.y * x1.x;
        float dr = zr - y1.x;
        float di = zi - y1.y;
        acc1.x += Hv.x * dr + Hv.y * di;
        acc1.y += Hv.x * di - Hv.y * dr;
    }
    {   // batch 1, pixel B
        float zr = Hv.z * x1.z - Hv.w * x1.w;
        float zi = Hv.z * x1.w + Hv.w * x1.z;
        float dr = zr - y1.z;
        float di = zi - y1.w;
        acc1.z += Hv.z * dr + Hv.w * di;
        acc1.w += Hv.z * di - Hv.w * dr;
    }
}

__global__ __launch_bounds__(128) void idt_backproj_kernel(
    const float4* __restrict__ x,   // f_ipt  [2][HW4]
    const float4* __restrict__ y,   // f_y    [2][NFRAMES][HW4]
    const float4* __restrict__ Hm,  // Hreal  [NFRAMES][HW4]
    const int*    __restrict__ nbf, // scalar
    float4*       __restrict__ out) // [2][HW4]
{
    const int p = blockIdx.x * blockDim.x + threadIdx.x;

    const float4 x0 = x[p];
    const float4 x1 = x[HW4 + p];

    float4 acc0 = make_float4(0.f, 0.f, 0.f, 0.f);
    float4 acc1 = make_float4(0.f, 0.f, 0.f, 0.f);

    const float4* Hp  = Hm + p;
    const float4* y0p = y + p;                              // batch 0
    const float4* y1p = y + (size_t)NFRAMES * HW4 + p;      // batch 1

    // Frames 0..NPIN-1: H via normal-policy load -> L2-retained across replays
#pragma unroll 4
    for (int n = 0; n < NPIN; n++) {
        const size_t off = (size_t)n * HW4;
        const float4 Hv = __ldcg(Hp  + off);
        const float4 y0 = __ldcs(y0p + off);
        const float4 y1 = __ldcs(y1p + off);
        cstep4(Hv, x0, x1, y0, y1, acc0, acc1);
    }

    // Frames NPIN..63: everything streams evict-first
#pragma unroll 4
    for (int n = NPIN; n < NFRAMES; n++) {
        const size_t off = (size_t)n * HW4;
        const float4 Hv = __ldcs(Hp  + off);
        const float4 y0 = __ldcs(y0p + off);
        const float4 y1 = __ldcs(y1p + off);
        cstep4(Hv, x0, x1, y0, y1, acc0, acc1);
    }

    const float scale = 1.0f / (float)(*nbf);
    acc0.x *= scale; acc0.y *= scale; acc0.z *= scale; acc0.w *= scale;
    acc1.x *= scale; acc1.y *= scale; acc1.z *= scale; acc1.w *= scale;

    // Write-through stores: result is never re-read, keep it out of L2.
    __stwt(out + p,       acc0);
    __stwt(out + HW4 + p, acc1);
}

extern "C" void kernel_launch(void* const* d_in, const int* in_sizes, int n_in,
                              void* d_out, int out_size) {
    const float4* x   = (const float4*)d_in[0];
    const float4* y   = (const float4*)d_in[1];
    const float4* Hm  = (const float4*)d_in[2];
    const int*    nbf = (const int*)d_in[3];
    float4*       out = (float4*)d_out;

    const int threads = 128;
    const int blocks  = HW4 / threads;  // 1024
    idt_backproj_kernel<<<blocks, threads>>>(x, y, Hm, nbf, out);
}